// round 6
// baseline (speedup 1.0000x reference)
#include <cuda_runtime.h>
#include <cstdint>

#define Bn   8
#define Cin  64
#define Hh   128
#define Ww   128
#define HW   (Hh*Ww)
#define Cout 64
#define CIN2 66
#define KDIM 594   // CIN2 * 9
#define CHOM 27
#define NCHUNK 33  // 2 channels per chunk; chunk 32 = coord channels (analytic)

// ---------------- scratch (static device memory; no allocations) ----------------
__device__ float g_off [Bn*18*Hh*Ww];   // raw om channels 0..17
__device__ float g_mask[Bn*9*Hh*Ww];    // sigmoid(mask)
__device__ float g_wt  [KDIM*Cout];     // transposed main weight [k][o]

// ---------------- packed f32x2 helpers (base Blackwell ISA, sm_100+) ----------------
__device__ __forceinline__ unsigned long long pack2(float a, float b) {
    unsigned long long r;
    asm("mov.b64 %0, {%1,%2};" : "=l"(r) : "f"(a), "f"(b));
    return r;
}
__device__ __forceinline__ unsigned long long bcast2(float a) {
    unsigned long long r;
    asm("mov.b64 %0, {%1,%1};" : "=l"(r) : "f"(a));
    return r;
}
__device__ __forceinline__ void unpack2(unsigned long long v, float& a, float& b) {
    asm("mov.b64 {%0,%1}, %2;" : "=f"(a), "=f"(b) : "l"(v));
}
__device__ __forceinline__ void ffma2(unsigned long long& d,
                                      unsigned long long a, unsigned long long b) {
    asm("fma.rn.f32x2 %0, %1, %2, %0;" : "+l"(d) : "l"(a), "l"(b));
}

// ---------------- weight transpose prep ----------------
__global__ void prep_wt_kernel(const float* __restrict__ w)
{
    int i = blockIdx.x * 256 + threadIdx.x;
    if (i < Cout * KDIM) {
        int o = i / KDIM;
        int k = i - o * KDIM;
        g_wt[k * Cout + o] = w[i];
    }
}

// ---------------- Kernel A: offset/mask conv (27 oc, 66 ic, 3x3, pad 1) ----------------
__global__ void __launch_bounds__(128) om_conv_kernel(
    const float* __restrict__ input,
    const float* __restrict__ w_om,
    const float* __restrict__ b_om,
    float* __restrict__ idx_out,
    float* __restrict__ mask_out)
{
    extern __shared__ float sm[];
    float* sw   = sm;                 // KDIM * 28 floats
    float* rows = sm + KDIM * 28;     // 2 buffers * 3 rows * 132 floats

    const int tx = threadIdx.x;
    const int y  = blockIdx.x;
    const int b  = blockIdx.y;
    const float inv = 1.0f / 128.0f;

    for (int i = tx; i < CHOM * KDIM; i += 128) {
        int oc  = i / KDIM;
        int rem = i - oc * KDIM;        // rem = c*9 + t
        sw[rem * 28 + oc] = w_om[i];
    }

    unsigned long long acc2[14];
#pragma unroll
    for (int j = 0; j < 13; j++) acc2[j] = pack2(b_om[2 * j], b_om[2 * j + 1]);
    acc2[13] = pack2(b_om[26], 0.0f);

    auto stage = [&](int c, int buf) {
        float* dst = rows + buf * 396;
        for (int s = tx; s < 390; s += 128) {
            int r  = s / 130;
            int i  = s - r * 130;
            int yy = y + r - 1;
            int xx = i - 1;
            float val = 0.0f;
            if (yy >= 0 && yy < Hh && xx >= 0 && xx < Ww) {
                if (c < Cin)       val = input[(((b * Cin) + c) * Hh + yy) * Ww + xx];
                else if (c == Cin) val = yy * inv;
                else               val = xx * inv - 0.5f;
            }
            dst[r * 132 + i] = val;
        }
    };

    stage(0, 0);
    for (int c = 0; c < CIN2; c++) {
        __syncthreads();
        if (c + 1 < CIN2) stage(c + 1, (c + 1) & 1);
        const float* rb = rows + (c & 1) * 396;
        const float* wc = sw + c * 252;
#pragma unroll
        for (int t = 0; t < 9; t++) {
            unsigned long long vp = bcast2(rb[(t / 3) * 132 + tx + (t % 3)]);
            const ulonglong2* w2 = reinterpret_cast<const ulonglong2*>(wc + t * 28);
#pragma unroll
            for (int q = 0; q < 7; q++) {
                ulonglong2 wv = w2[q];
                ffma2(acc2[2 * q],     vp, wv.x);
                ffma2(acc2[2 * q + 1], vp, wv.y);
            }
        }
    }

    float acc[28];
#pragma unroll
    for (int j = 0; j < 14; j++) unpack2(acc2[j], acc[2 * j], acc[2 * j + 1]);

    const int x = tx;
#pragma unroll
    for (int j = 0; j < 9; j++) {
        int o = ((b * 18 + j) * Hh + y) * Ww + x;
        g_off[o]   = acc[j];
        idx_out[o] = y * inv + (float)(j / 3 - 1) + acc[j];
    }
#pragma unroll
    for (int j = 0; j < 9; j++) {
        int o = ((b * 18 + 9 + j) * Hh + y) * Ww + x;
        g_off[o]   = acc[9 + j];
        idx_out[o] = x * inv - 0.5f + (float)(j % 3 - 1) + acc[9 + j];
    }
#pragma unroll
    for (int j = 0; j < 9; j++) {
        float s = 1.0f / (1.0f + __expf(-acc[18 + j]));
        int o = ((b * 9 + j) * Hh + y) * Ww + x;
        g_mask[o]   = s;
        mask_out[o] = s;
    }
}

// ---------------- Kernel B: warp-specialized gather + GEMM (f32x2 consumers) ----------------
// 384 threads: tid 0..255 = consumers (GEMM), tid 256..383 = producers (gather).
// Double-buffered 2-channel chunks. Tap t's (h,w) offsets are om channels (2t, 2t+1).
__global__ void __launch_bounds__(384, 2) dcn_kernel(
    const float* __restrict__ input,
    const float* __restrict__ bias,
    float* __restrict__ out)
{
    extern __shared__ float sm[];
    int4*   sIdx = (int4*)sm;                       // [9*128]
    float4* sWt  = (float4*)(sm + 1152 * 4);        // [9*128]
    float*  cols = sm + 1152 * 8;                   // [2][18*128]

    const int tid = threadIdx.x;
    const int y   = blockIdx.x;
    const int b   = blockIdx.y;
    const float inv = 1.0f / 128.0f;

    // ---- phase 0 (all threads): per-(tap, pixel) bilinear corner data ----
    for (int q = tid; q < 9 * 128; q += 384) {
        int t = q >> 7;
        int p = q & 127;
        float oh = g_off [((b * 18 + 2 * t)     * Hh + y) * Ww + p];
        float ow = g_off [((b * 18 + 2 * t + 1) * Hh + y) * Ww + p];
        float mk = g_mask[((b * 9 + t)          * Hh + y) * Ww + p];

        float ph = oh + (float)(t / 3) + (float)(y - 1);
        float pw = ow + (float)(t % 3) + (float)(p - 1);
        float h0f = floorf(ph), w0f = floorf(pw);
        float lh = ph - h0f, lw = pw - w0f;
        float hh = 1.0f - lh, hw = 1.0f - lw;
        int h0 = (int)h0f, w0 = (int)w0f;
        int h1 = h0 + 1,   w1 = w0 + 1;
        float okh0 = (h0 >= 0 && h0 < Hh) ? 1.0f : 0.0f;
        float okh1 = (h1 >= 0 && h1 < Hh) ? 1.0f : 0.0f;
        float okw0 = (w0 >= 0 && w0 < Ww) ? 1.0f : 0.0f;
        float okw1 = (w1 >= 0 && w1 < Ww) ? 1.0f : 0.0f;
        float w00 = hh * hw * okh0 * okw0 * mk;
        float w01 = hh * lw * okh0 * okw1 * mk;
        float w10 = lh * hw * okh1 * okw0 * mk;
        float w11 = lh * lw * okh1 * okw1 * mk;
        int h0c = min(max(h0, 0), Hh - 1), h1c = min(max(h1, 0), Hh - 1);
        int w0c = min(max(w0, 0), Ww - 1), w1c = min(max(w1, 0), Ww - 1);

        sIdx[q] = make_int4(h0c * Ww, h1c * Ww, w0c, w1c);
        sWt[q]  = make_float4(w00, w01, w10, w11);
    }
    __syncthreads();

    const float* binp = input + b * Cin * HW;

    if (tid >= 256) {
        // ================= PRODUCER (warps 8-11) =================
        const int ptid = tid - 256;   // 0..127 : one pixel per thread

        auto produce = [&](int cn, int buf) {
            float* dst = cols + buf * 2304 + ptid;
            if (cn < 32) {
                const float* pl0 = binp + (2 * cn) * HW;
                const float* pl1 = pl0 + HW;
#pragma unroll
                for (int t = 0; t < 9; t++) {
                    int q = t * 128 + ptid;
                    int4   id = sIdx[q];
                    float4 wt = sWt[q];
                    int a00 = id.x + id.z, a01 = id.x + id.w;
                    int a10 = id.y + id.z, a11 = id.y + id.w;
                    float v0 = wt.x * pl0[a00] + wt.y * pl0[a01]
                             + wt.z * pl0[a10] + wt.w * pl0[a11];
                    float v1 = wt.x * pl1[a00] + wt.y * pl1[a01]
                             + wt.z * pl1[a10] + wt.w * pl1[a11];
                    dst[t * 128]       = v0;
                    dst[(9 + t) * 128] = v1;
                }
            } else {
#pragma unroll
                for (int t = 0; t < 9; t++) {
                    int q = t * 128 + ptid;
                    int4   id = sIdx[q];
                    float4 wt = sWt[q];
                    dst[t * 128] = ((wt.x + wt.y) * (float)(id.x >> 7)
                                  + (wt.z + wt.w) * (float)(id.y >> 7)) * inv;
                    dst[(9 + t) * 128] =
                          (wt.x + wt.z) * ((float)id.z * inv - 0.5f)
                        + (wt.y + wt.w) * ((float)id.w * inv - 0.5f);
                }
            }
        };

        produce(0, 0);
        __syncthreads();
        for (int c = 0; c < NCHUNK; c++) {
            if (c + 1 < NCHUNK) produce(c + 1, (c + 1) & 1);
            __syncthreads();
        }
    } else {
        // ================= CONSUMER (warps 0-7): f32x2 GEMM =================
        const int og = tid >> 4;   // 0..15 -> 4 out channels
        const int pg = tid & 15;   // 0..15 -> 8 pixels (4 f32x2 pairs)
        unsigned long long acc2[4][4];
#pragma unroll
        for (int i = 0; i < 4; i++)
#pragma unroll
            for (int j = 0; j < 4; j++) acc2[i][j] = 0ULL;

        __syncthreads();   // matches producer's post-produce(0) barrier
        for (int c = 0; c < NCHUNK; c++) {
            const float* cb = cols + (c & 1) * 2304 + pg * 8;
            const float* wb = g_wt + (c * 18) * Cout + og * 4;
#pragma unroll 6
            for (int kk = 0; kk < 18; kk++) {
                float4 wv = __ldg(reinterpret_cast<const float4*>(wb + kk * Cout));
                ulonglong2 c01 = *reinterpret_cast<const ulonglong2*>(cb + kk * 128);
                ulonglong2 c23 = *reinterpret_cast<const ulonglong2*>(cb + kk * 128 + 4);
                unsigned long long wp0 = bcast2(wv.x);
                unsigned long long wp1 = bcast2(wv.y);
                unsigned long long wp2 = bcast2(wv.z);
                unsigned long long wp3 = bcast2(wv.w);
                ffma2(acc2[0][0], wp0, c01.x); ffma2(acc2[0][1], wp0, c01.y);
                ffma2(acc2[0][2], wp0, c23.x); ffma2(acc2[0][3], wp0, c23.y);
                ffma2(acc2[1][0], wp1, c01.x); ffma2(acc2[1][1], wp1, c01.y);
                ffma2(acc2[1][2], wp1, c23.x); ffma2(acc2[1][3], wp1, c23.y);
                ffma2(acc2[2][0], wp2, c01.x); ffma2(acc2[2][1], wp2, c01.y);
                ffma2(acc2[2][2], wp2, c23.x); ffma2(acc2[2][3], wp2, c23.y);
                ffma2(acc2[3][0], wp3, c01.x); ffma2(acc2[3][1], wp3, c01.y);
                ffma2(acc2[3][2], wp3, c23.x); ffma2(acc2[3][3], wp3, c23.y);
            }
            __syncthreads();
        }

#pragma unroll
        for (int i = 0; i < 4; i++) {
            float bv = bias[og * 4 + i];
            float a0, a1, a2, a3, a4, a5, a6, a7;
            unpack2(acc2[i][0], a0, a1);
            unpack2(acc2[i][1], a2, a3);
            unpack2(acc2[i][2], a4, a5);
            unpack2(acc2[i][3], a6, a7);
            float* op = out + ((b * Cout + og * 4 + i) * Hh + y) * Ww + pg * 8;
            float4 o0 = make_float4(a0 + bv, a1 + bv, a2 + bv, a3 + bv);
            float4 o1 = make_float4(a4 + bv, a5 + bv, a6 + bv, a7 + bv);
            *reinterpret_cast<float4*>(op)     = o0;
            *reinterpret_cast<float4*>(op + 4) = o1;
        }
    }
}

// ---------------- launcher ----------------
extern "C" void kernel_launch(void* const* d_in, const int* in_sizes, int n_in,
                              void* d_out, int out_size)
{
    const float* input  = (const float*)d_in[0];
    const float* weight = (const float*)d_in[1];
    const float* bias   = (const float*)d_in[2];
    const float* w_om   = (const float*)d_in[3];
    const float* b_om   = (const float*)d_in[4];

    float* out      = (float*)d_out;
    float* idx_out  = out + (size_t)Bn * Cout * Hh * Ww;
    float* mask_out = idx_out + (size_t)Bn * 18 * Hh * Ww;

    const int smA = (KDIM * 28 + 2 * 396) * 4;                 // 69,696 B
    const int smB = (1152 * 8 + 2 * 2304) * 4;                 // 55,296 B
    cudaFuncSetAttribute(om_conv_kernel, cudaFuncAttributeMaxDynamicSharedMemorySize, smA);
    cudaFuncSetAttribute(dcn_kernel,     cudaFuncAttributeMaxDynamicSharedMemorySize, smB);

    prep_wt_kernel<<<(Cout * KDIM + 255) / 256, 256>>>(weight);
    om_conv_kernel<<<dim3(Hh, Bn), 128, smA>>>(input, w_om, b_om, idx_out, mask_out);
    dcn_kernel<<<dim3(Hh, Bn), 384, smB>>>(input, bias, out);
}

// round 7
// speedup vs baseline: 1.0501x; 1.0501x over previous
#include <cuda_runtime.h>

#define Bn   8
#define Cin  64
#define Hh   128
#define Ww   128
#define HW   (Hh*Ww)
#define Cout 64
#define CIN2 66
#define KDIM 594   // CIN2 * 9
#define CHOM 27
#define NCHUNK 33  // 2 channels per chunk; chunk 32 = coord channels (analytic)

// ---------------- scratch ----------------
__device__ float g_wt[KDIM*Cout];   // transposed main weight [k][o]

// ---------------- weight transpose prep ----------------
__global__ void prep_wt_kernel(const float* __restrict__ w)
{
    int i = blockIdx.x * 256 + threadIdx.x;
    if (i < Cout * KDIM) {
        int o = i / KDIM;
        int k = i - o * KDIM;
        g_wt[k * Cout + o] = w[i];
    }
}

// ---------------- fused kernel: om conv + deformable gather + GEMM ----------------
// One block per (row y, batch b); 384 threads.
// Phase B: om conv, 3 oc-groups (warps 0-3: oc 0-8, 4-7: oc 9-17, 8-11: oc 18-26)
//          x 128 px. Writes idx/mask outputs + om_buf (smem).
// Phase C: bilinear corner tables.
// Phase D: warp-specialized gather (warps 8-11) + GEMM (warps 0-7), as R4.
// Smem union: [0..66528B) sw  -> reused as sIdx/sWt/cols in C/D.
//             [66528..69696B) rows ; [69696..83520B) om_buf[27][128].
__global__ void __launch_bounds__(384, 2) fused_kernel(
    const float* __restrict__ input,
    const float* __restrict__ w_om,
    const float* __restrict__ b_om,
    const float* __restrict__ bias,
    float* __restrict__ out,
    float* __restrict__ idx_out,
    float* __restrict__ mask_out)
{
    extern __shared__ float sm[];
    float*  sw   = sm;                        // [594][28]
    float*  rows = sm + 16632;                // 2 * 396
    float*  omb  = sm + 17424;                // [27][128]
    int4*   sIdx = (int4*)sm;                 // [1152]  (phase C/D)
    float4* sWt  = (float4*)(sm + 4608);      // [1152]
    float*  cols = sm + 9216;                 // [2][2304]

    const int tid = threadIdx.x;
    const int y   = blockIdx.x;
    const int b   = blockIdx.y;
    const float inv = 1.0f / 128.0f;

    // ---- phase A: stage om weights, transposed [(c*9+t)][oc] ----
    for (int i = tid; i < CHOM * KDIM; i += 384) {
        int oc  = i / KDIM;
        int rem = i - oc * KDIM;
        sw[rem * 28 + oc] = w_om[i];
    }

    // ---- phase B: om conv ----
    const int g  = tid >> 7;     // oc group 0..2
    const int px = tid & 127;
    float acc[9];
#pragma unroll
    for (int j = 0; j < 9; j++) acc[j] = b_om[g * 9 + j];

    auto stage = [&](int c, int buf) {
        float* dst = rows + buf * 396;
        for (int s = tid; s < 390; s += 384) {
            int r  = s / 130;
            int i  = s - r * 130;
            int yy = y + r - 1;
            int xx = i - 1;
            float val = 0.0f;
            if (yy >= 0 && yy < Hh && xx >= 0 && xx < Ww) {
                if (c < Cin)       val = input[(((b * Cin) + c) * Hh + yy) * Ww + xx];
                else if (c == Cin) val = yy * inv;
                else               val = xx * inv - 0.5f;
            }
            dst[r * 132 + i] = val;
        }
    };

    stage(0, 0);
    for (int c = 0; c < CIN2; c++) {
        __syncthreads();
        if (c + 1 < CIN2) stage(c + 1, (c + 1) & 1);
        const float* rb = rows + (c & 1) * 396;
        const float* wb = sw + c * 252 + g * 9;   // broadcast reads (warp-uniform g)
#pragma unroll
        for (int t = 0; t < 9; t++) {
            float v = rb[(t / 3) * 132 + px + (t % 3)];
#pragma unroll
            for (int j = 0; j < 9; j++) acc[j] += v * wb[t * 28 + j];
        }
    }

    // emit idx / mask outputs and om_buf
    if (g < 2) {
#pragma unroll
        for (int j = 0; j < 9; j++) {
            int oc = g * 9 + j;
            float base_ = (g == 0)
                ? (y * inv + (float)(j / 3 - 1))
                : (px * inv - 0.5f + (float)(j % 3 - 1));
            idx_out[((b * 18 + oc) * Hh + y) * Ww + px] = base_ + acc[j];
            omb[oc * 128 + px] = acc[j];
        }
    } else {
#pragma unroll
        for (int j = 0; j < 9; j++) {
            float s = 1.0f / (1.0f + __expf(-acc[j]));
            mask_out[((b * 9 + j) * Hh + y) * Ww + px] = s;
            omb[(18 + j) * 128 + px] = s;
        }
    }
    __syncthreads();

    // ---- phase C: bilinear corner tables (overwrites sw region) ----
    for (int q = tid; q < 9 * 128; q += 384) {
        int t = q >> 7;
        int p = q & 127;
        float oh = omb[(2 * t) * 128 + p];
        float ow = omb[(2 * t + 1) * 128 + p];
        float mk = omb[(18 + t) * 128 + p];

        float ph = oh + (float)(t / 3) + (float)(y - 1);
        float pw = ow + (float)(t % 3) + (float)(p - 1);
        float h0f = floorf(ph), w0f = floorf(pw);
        float lh = ph - h0f, lw = pw - w0f;
        float hh = 1.0f - lh, hw = 1.0f - lw;
        int h0 = (int)h0f, w0 = (int)w0f;
        int h1 = h0 + 1,   w1 = w0 + 1;
        float okh0 = (h0 >= 0 && h0 < Hh) ? 1.0f : 0.0f;
        float okh1 = (h1 >= 0 && h1 < Hh) ? 1.0f : 0.0f;
        float okw0 = (w0 >= 0 && w0 < Ww) ? 1.0f : 0.0f;
        float okw1 = (w1 >= 0 && w1 < Ww) ? 1.0f : 0.0f;
        float w00 = hh * hw * okh0 * okw0 * mk;
        float w01 = hh * lw * okh0 * okw1 * mk;
        float w10 = lh * hw * okh1 * okw0 * mk;
        float w11 = lh * lw * okh1 * okw1 * mk;
        int h0c = min(max(h0, 0), Hh - 1), h1c = min(max(h1, 0), Hh - 1);
        int w0c = min(max(w0, 0), Ww - 1), w1c = min(max(w1, 0), Ww - 1);

        sIdx[q] = make_int4(h0c * Ww, h1c * Ww, w0c, w1c);
        sWt[q]  = make_float4(w00, w01, w10, w11);
    }
    __syncthreads();

    // ---- phase D: warp-specialized gather + GEMM ----
    const float* binp = input + b * Cin * HW;

    if (tid >= 256) {
        // producers (warps 8-11): one pixel per thread
        const int ptid = tid - 256;

        auto produce = [&](int cn, int buf) {
            float* dst = cols + buf * 2304 + ptid;
            if (cn < 32) {
                const float* pl0 = binp + (2 * cn) * HW;
                const float* pl1 = pl0 + HW;
#pragma unroll
                for (int t = 0; t < 9; t++) {
                    int q = t * 128 + ptid;
                    int4   id = sIdx[q];
                    float4 wt = sWt[q];
                    int a00 = id.x + id.z, a01 = id.x + id.w;
                    int a10 = id.y + id.z, a11 = id.y + id.w;
                    float v0 = wt.x * pl0[a00] + wt.y * pl0[a01]
                             + wt.z * pl0[a10] + wt.w * pl0[a11];
                    float v1 = wt.x * pl1[a00] + wt.y * pl1[a01]
                             + wt.z * pl1[a10] + wt.w * pl1[a11];
                    dst[t * 128]       = v0;
                    dst[(9 + t) * 128] = v1;
                }
            } else {
#pragma unroll
                for (int t = 0; t < 9; t++) {
                    int q = t * 128 + ptid;
                    int4   id = sIdx[q];
                    float4 wt = sWt[q];
                    dst[t * 128] = ((wt.x + wt.y) * (float)(id.x >> 7)
                                  + (wt.z + wt.w) * (float)(id.y >> 7)) * inv;
                    dst[(9 + t) * 128] =
                          (wt.x + wt.z) * ((float)id.z * inv - 0.5f)
                        + (wt.y + wt.w) * ((float)id.w * inv - 0.5f);
                }
            }
        };

        produce(0, 0);
        __syncthreads();
        for (int c = 0; c < NCHUNK; c++) {
            if (c + 1 < NCHUNK) produce(c + 1, (c + 1) & 1);
            __syncthreads();
        }
    } else {
        // consumers (warps 0-7): scalar-FFMA GEMM, 4 oc x 8 px per thread
        const int og = tid >> 4;
        const int pg = tid & 15;
        float dacc[4][8];
#pragma unroll
        for (int i = 0; i < 4; i++)
#pragma unroll
            for (int j = 0; j < 8; j++) dacc[i][j] = 0.0f;

        __syncthreads();   // matches producer's post-produce(0) barrier
        for (int c = 0; c < NCHUNK; c++) {
            const float* cb = cols + (c & 1) * 2304 + pg * 8;
            const float* wb = g_wt + (c * 18) * Cout + og * 4;
#pragma unroll 6
            for (int kk = 0; kk < 18; kk++) {
                float4 wv  = __ldg(reinterpret_cast<const float4*>(wb + kk * Cout));
                float4 cv0 = *reinterpret_cast<const float4*>(cb + kk * 128);
                float4 cv1 = *reinterpret_cast<const float4*>(cb + kk * 128 + 4);
#pragma unroll
                for (int i = 0; i < 4; i++) {
                    float w = (i == 0) ? wv.x : (i == 1) ? wv.y : (i == 2) ? wv.z : wv.w;
                    dacc[i][0] += w * cv0.x; dacc[i][1] += w * cv0.y;
                    dacc[i][2] += w * cv0.z; dacc[i][3] += w * cv0.w;
                    dacc[i][4] += w * cv1.x; dacc[i][5] += w * cv1.y;
                    dacc[i][6] += w * cv1.z; dacc[i][7] += w * cv1.w;
                }
            }
            __syncthreads();
        }

#pragma unroll
        for (int i = 0; i < 4; i++) {
            float bv = bias[og * 4 + i];
            float* op = out + ((b * Cout + og * 4 + i) * Hh + y) * Ww + pg * 8;
            float4 o0 = make_float4(dacc[i][0] + bv, dacc[i][1] + bv,
                                    dacc[i][2] + bv, dacc[i][3] + bv);
            float4 o1 = make_float4(dacc[i][4] + bv, dacc[i][5] + bv,
                                    dacc[i][6] + bv, dacc[i][7] + bv);
            *reinterpret_cast<float4*>(op)     = o0;
            *reinterpret_cast<float4*>(op + 4) = o1;
        }
    }
}

// ---------------- launcher ----------------
extern "C" void kernel_launch(void* const* d_in, const int* in_sizes, int n_in,
                              void* d_out, int out_size)
{
    const float* input  = (const float*)d_in[0];
    const float* weight = (const float*)d_in[1];
    const float* bias   = (const float*)d_in[2];
    const float* w_om   = (const float*)d_in[3];
    const float* b_om   = (const float*)d_in[4];

    float* out      = (float*)d_out;
    float* idx_out  = out + (size_t)Bn * Cout * Hh * Ww;
    float* mask_out = idx_out + (size_t)Bn * 18 * Hh * Ww;

    const int smF = 20880 * 4;   // 83,520 B
    cudaFuncSetAttribute(fused_kernel, cudaFuncAttributeMaxDynamicSharedMemorySize, smF);

    prep_wt_kernel<<<(Cout * KDIM + 255) / 256, 256>>>(weight);
    fused_kernel<<<dim3(Hh, Bn), 384, smF>>>(input, w_om, b_om, bias,
                                             out, idx_out, mask_out);
}

// round 8
// speedup vs baseline: 1.5101x; 1.4381x over previous
#include <cuda_runtime.h>

#define Bn   8
#define Cin  64
#define Hh   128
#define Ww   128
#define HW   (Hh*Ww)
#define Cout 64
#define CIN2 66
#define KDIM 594   // CIN2 * 9
#define CHOM 27
#define NCHUNK 33  // 2 channels per chunk; chunk 32 = coord channels (analytic)

// ---------------- scratch ----------------
__device__ float g_wt[KDIM*Cout];   // transposed main weight [k][o]

__global__ void prep_wt_kernel(const float* __restrict__ w)
{
    int i = blockIdx.x * 256 + threadIdx.x;
    if (i < Cout * KDIM) {
        int o = i / KDIM;
        int k = i - o * KDIM;
        g_wt[k * Cout + o] = w[i];
    }
}

// ---------------- fused kernel ----------------
// One block per (row y, batch b); 384 threads.
// Phase B: om conv, c-split into 3 groups of 22 channels (named barriers),
//          each thread computes all 28 oc for its pixel over its c-range;
//          groups 1,2 dump partials to smem, group 0 reduces + emits.
// Phase C: bilinear corner tables. Phase D: producer/consumer gather+GEMM.
// Smem (floats): sw[0,16632) -> reused as sIdx/sWt/cols in C/D;
//   rows [16632,19008) (3 groups x 2 bufs x 396);
//   pbuf [19008,26176) (2 x 128 x 28), p1 reused as omb[27][128].
__global__ void __launch_bounds__(384, 2) fused_kernel(
    const float* __restrict__ input,
    const float* __restrict__ w_om,
    const float* __restrict__ b_om,
    const float* __restrict__ bias,
    float* __restrict__ out,
    float* __restrict__ idx_out,
    float* __restrict__ mask_out)
{
    extern __shared__ float sm[];
    float*  sw   = sm;                        // [594][28]
    float*  rows = sm + 16632;                // 3 * 2 * 396
    float*  p1   = sm + 19008;                // [28][128] partial g1
    float*  p2   = sm + 22592;                // [28][128] partial g2
    float*  omb  = sm + 19008;                // [27][128] (reuses p1)
    int4*   sIdx = (int4*)sm;                 // [1152]  (phase C/D)
    float4* sWt  = (float4*)(sm + 4608);      // [1152]
    float*  cols = sm + 9216;                 // [2][2304]

    const int tid = threadIdx.x;
    const int y   = blockIdx.x;
    const int b   = blockIdx.y;
    const float inv = 1.0f / 128.0f;

    // ---- phase A: stage om weights, transposed [(c*9+t)][oc] ----
    for (int i = tid; i < CHOM * KDIM; i += 384) {
        int oc  = i / KDIM;
        int rem = i - oc * KDIM;
        sw[rem * 28 + oc] = w_om[i];
    }

    // ---- phase B: om conv, c-split over 3 groups ----
    const int g   = tid >> 7;      // 0..2
    const int px  = tid & 127;
    const int cb0 = g * 22;

    float acc[28];
#pragma unroll
    for (int j = 0; j < 27; j++) acc[j] = (g == 0) ? b_om[j] : 0.0f;
    acc[27] = 0.0f;

    auto stage = [&](int c, int buf) {
        float* dst = rows + (g * 2 + buf) * 396;
        for (int s = px; s < 390; s += 128) {
            int r  = s / 130;
            int i  = s - r * 130;
            int yy = y + r - 1;
            int xx = i - 1;
            float val = 0.0f;
            if (yy >= 0 && yy < Hh && xx >= 0 && xx < Ww) {
                if (c < Cin)       val = input[(((b * Cin) + c) * Hh + yy) * Ww + xx];
                else if (c == Cin) val = yy * inv;
                else               val = xx * inv - 0.5f;
            }
            dst[r * 132 + i] = val;
        }
    };

    stage(cb0, 0);
    __syncthreads();   // sw ready (and first rows staged)

    for (int ci = 0; ci < 22; ci++) {
        asm volatile("bar.sync %0, %1;" :: "r"(g + 1), "r"(128) : "memory");
        if (ci + 1 < 22) stage(cb0 + ci + 1, (ci + 1) & 1);
        const float* rb = rows + (g * 2 + (ci & 1)) * 396;
        const float* wc = sw + (cb0 + ci) * 252;
#pragma unroll
        for (int t = 0; t < 9; t++) {
            float v = rb[(t / 3) * 132 + px + (t % 3)];
            const float4* w4 = reinterpret_cast<const float4*>(wc + t * 28);
#pragma unroll
            for (int q = 0; q < 7; q++) {
                float4 wv = w4[q];
                acc[q * 4 + 0] += v * wv.x;
                acc[q * 4 + 1] += v * wv.y;
                acc[q * 4 + 2] += v * wv.z;
                acc[q * 4 + 3] += v * wv.w;
            }
        }
    }

    // partial dump (groups 1,2), reduce + emit (group 0)
    if (g == 1) {
#pragma unroll
        for (int j = 0; j < 27; j++) p1[j * 128 + px] = acc[j];
    } else if (g == 2) {
#pragma unroll
        for (int j = 0; j < 27; j++) p2[j * 128 + px] = acc[j];
    }
    __syncthreads();
    if (g == 0) {
#pragma unroll
        for (int j = 0; j < 27; j++) {
            float a = acc[j] + p1[j * 128 + px] + p2[j * 128 + px];
            if (j < 9) {
                idx_out[((b * 18 + j) * Hh + y) * Ww + px] =
                    y * inv + (float)(j / 3 - 1) + a;
                omb[j * 128 + px] = a;
            } else if (j < 18) {
                int j2 = j - 9;
                idx_out[((b * 18 + j) * Hh + y) * Ww + px] =
                    px * inv - 0.5f + (float)(j2 % 3 - 1) + a;
                omb[j * 128 + px] = a;
            } else {
                float s = 1.0f / (1.0f + __expf(-a));
                mask_out[((b * 9 + (j - 18)) * Hh + y) * Ww + px] = s;
                omb[j * 128 + px] = s;
            }
        }
    }
    __syncthreads();

    // ---- phase C: bilinear corner tables (overwrites sw region) ----
    for (int q = tid; q < 9 * 128; q += 384) {
        int t = q >> 7;
        int p = q & 127;
        float oh = omb[(2 * t) * 128 + p];
        float ow = omb[(2 * t + 1) * 128 + p];
        float mk = omb[(18 + t) * 128 + p];

        float ph = oh + (float)(t / 3) + (float)(y - 1);
        float pw = ow + (float)(t % 3) + (float)(p - 1);
        float h0f = floorf(ph), w0f = floorf(pw);
        float lh = ph - h0f, lw = pw - w0f;
        float hh = 1.0f - lh, hw = 1.0f - lw;
        int h0 = (int)h0f, w0 = (int)w0f;
        int h1 = h0 + 1,   w1 = w0 + 1;
        float okh0 = (h0 >= 0 && h0 < Hh) ? 1.0f : 0.0f;
        float okh1 = (h1 >= 0 && h1 < Hh) ? 1.0f : 0.0f;
        float okw0 = (w0 >= 0 && w0 < Ww) ? 1.0f : 0.0f;
        float okw1 = (w1 >= 0 && w1 < Ww) ? 1.0f : 0.0f;
        float w00 = hh * hw * okh0 * okw0 * mk;
        float w01 = hh * lw * okh0 * okw1 * mk;
        float w10 = lh * hw * okh1 * okw0 * mk;
        float w11 = lh * lw * okh1 * okw1 * mk;
        int h0c = min(max(h0, 0), Hh - 1), h1c = min(max(h1, 0), Hh - 1);
        int w0c = min(max(w0, 0), Ww - 1), w1c = min(max(w1, 0), Ww - 1);

        sIdx[q] = make_int4(h0c * Ww, h1c * Ww, w0c, w1c);
        sWt[q]  = make_float4(w00, w01, w10, w11);
    }
    __syncthreads();

    // ---- phase D: warp-specialized gather + GEMM ----
    const float* binp = input + b * Cin * HW;

    if (tid >= 256) {
        // producers (warps 8-11): one pixel per thread
        const int ptid = tid - 256;

        auto produce = [&](int cn, int buf) {
            float* dst = cols + buf * 2304 + ptid;
            if (cn < 32) {
                const float* pl0 = binp + (2 * cn) * HW;
                const float* pl1 = pl0 + HW;
#pragma unroll
                for (int t = 0; t < 9; t++) {
                    int q = t * 128 + ptid;
                    int4   id = sIdx[q];
                    float4 wt = sWt[q];
                    int a00 = id.x + id.z, a01 = id.x + id.w;
                    int a10 = id.y + id.z, a11 = id.y + id.w;
                    float v0 = wt.x * pl0[a00] + wt.y * pl0[a01]
                             + wt.z * pl0[a10] + wt.w * pl0[a11];
                    float v1 = wt.x * pl1[a00] + wt.y * pl1[a01]
                             + wt.z * pl1[a10] + wt.w * pl1[a11];
                    dst[t * 128]       = v0;
                    dst[(9 + t) * 128] = v1;
                }
            } else {
#pragma unroll
                for (int t = 0; t < 9; t++) {
                    int q = t * 128 + ptid;
                    int4   id = sIdx[q];
                    float4 wt = sWt[q];
                    dst[t * 128] = ((wt.x + wt.y) * (float)(id.x >> 7)
                                  + (wt.z + wt.w) * (float)(id.y >> 7)) * inv;
                    dst[(9 + t) * 128] =
                          (wt.x + wt.z) * ((float)id.z * inv - 0.5f)
                        + (wt.y + wt.w) * ((float)id.w * inv - 0.5f);
                }
            }
        };

        produce(0, 0);
        __syncthreads();
        for (int c = 0; c < NCHUNK; c++) {
            if (c + 1 < NCHUNK) produce(c + 1, (c + 1) & 1);
            __syncthreads();
        }
    } else {
        // consumers (warps 0-7): 8 oc x 4 px per thread; og = warp id so the
        // weight LDGs are warp-uniform broadcasts.
        const int og = tid >> 5;   // 0..7  -> oc og*8 .. og*8+7
        const int pg = tid & 31;   // 0..31 -> px pg*4 .. pg*4+3
        float dacc[8][4];
#pragma unroll
        for (int i = 0; i < 8; i++)
#pragma unroll
            for (int j = 0; j < 4; j++) dacc[i][j] = 0.0f;

        __syncthreads();   // matches producer's post-produce(0) barrier
        for (int c = 0; c < NCHUNK; c++) {
            const float* cbp = cols + (c & 1) * 2304 + pg * 4;
            const float* wb  = g_wt + (c * 18) * Cout + og * 8;
#pragma unroll 6
            for (int kk = 0; kk < 18; kk++) {
                float4 w0 = __ldg(reinterpret_cast<const float4*>(wb + kk * Cout));
                float4 w1 = __ldg(reinterpret_cast<const float4*>(wb + kk * Cout + 4));
                float4 cv = *reinterpret_cast<const float4*>(cbp + kk * 128);
                dacc[0][0] += w0.x * cv.x; dacc[0][1] += w0.x * cv.y;
                dacc[0][2] += w0.x * cv.z; dacc[0][3] += w0.x * cv.w;
                dacc[1][0] += w0.y * cv.x; dacc[1][1] += w0.y * cv.y;
                dacc[1][2] += w0.y * cv.z; dacc[1][3] += w0.y * cv.w;
                dacc[2][0] += w0.z * cv.x; dacc[2][1] += w0.z * cv.y;
                dacc[2][2] += w0.z * cv.z; dacc[2][3] += w0.z * cv.w;
                dacc[3][0] += w0.w * cv.x; dacc[3][1] += w0.w * cv.y;
                dacc[3][2] += w0.w * cv.z; dacc[3][3] += w0.w * cv.w;
                dacc[4][0] += w1.x * cv.x; dacc[4][1] += w1.x * cv.y;
                dacc[4][2] += w1.x * cv.z; dacc[4][3] += w1.x * cv.w;
                dacc[5][0] += w1.y * cv.x; dacc[5][1] += w1.y * cv.y;
                dacc[5][2] += w1.y * cv.z; dacc[5][3] += w1.y * cv.w;
                dacc[6][0] += w1.z * cv.x; dacc[6][1] += w1.z * cv.y;
                dacc[6][2] += w1.z * cv.z; dacc[6][3] += w1.z * cv.w;
                dacc[7][0] += w1.w * cv.x; dacc[7][1] += w1.w * cv.y;
                dacc[7][2] += w1.w * cv.z; dacc[7][3] += w1.w * cv.w;
            }
            __syncthreads();
        }

#pragma unroll
        for (int i = 0; i < 8; i++) {
            int oc = og * 8 + i;
            float bv = bias[oc];
            float4 o = make_float4(dacc[i][0] + bv, dacc[i][1] + bv,
                                   dacc[i][2] + bv, dacc[i][3] + bv);
            *reinterpret_cast<float4*>(
                out + ((b * Cout + oc) * Hh + y) * Ww + pg * 4) = o;
        }
    }
}

// ---------------- launcher ----------------
extern "C" void kernel_launch(void* const* d_in, const int* in_sizes, int n_in,
                              void* d_out, int out_size)
{
    const float* input  = (const float*)d_in[0];
    const float* weight = (const float*)d_in[1];
    const float* bias   = (const float*)d_in[2];
    const float* w_om   = (const float*)d_in[3];
    const float* b_om   = (const float*)d_in[4];

    float* out      = (float*)d_out;
    float* idx_out  = out + (size_t)Bn * Cout * Hh * Ww;
    float* mask_out = idx_out + (size_t)Bn * 18 * Hh * Ww;

    const int smF = 26176 * 4;   // 104,704 B
    cudaFuncSetAttribute(fused_kernel, cudaFuncAttributeMaxDynamicSharedMemorySize, smF);

    prep_wt_kernel<<<(Cout * KDIM + 255) / 256, 256>>>(weight);
    fused_kernel<<<dim3(Hh, Bn), 384, smF>>>(input, w_om, b_om, bias,
                                             out, idx_out, mask_out);
}

// round 9
// speedup vs baseline: 1.6605x; 1.0996x over previous
#include <cuda_runtime.h>

#define Bn   8
#define Cin  64
#define Hh   128
#define Ww   128
#define HW   (Hh*Ww)
#define Cout 64
#define CIN2 66
#define KDIM 594    // CIN2 * 9
#define CHOM 27
#define NCHUNK 17   // 16 chunks x 4 ch + 1 chunk (coord ch 64,65 + pad)
#define KPAD 612    // 17 * 36

// ---------------- scratch ----------------
__device__ float g_wt[KPAD*Cout];   // transposed main weight [k][o], zero-padded

__global__ void prep_wt_kernel(const float* __restrict__ w)
{
    int i = blockIdx.x * 256 + threadIdx.x;
    if (i < KPAD * Cout) {
        int k = i >> 6;
        int o = i & 63;
        g_wt[i] = (k < KDIM) ? w[o * KDIM + k] : 0.0f;
    }
}

// ---------------- fused kernel ----------------
// One block per (row y, batch b); 384 threads.
// Phase B: om conv, 6 c-groups (11 ch) x 64 threads; thread = 2 px x 28 oc.
// Phase C: bilinear corner tables. Phase D: producers(128) gather 4-ch chunks,
// consumers(256, 8oc x 4px) GEMM.
// Smem floats: sw[0,16632) (reused: partials in B-tail, sIdx/sWt/cols in C/D);
//   rows [16632,21384) (6 groups x 2 x 396); omb [21384,24840).
__global__ void __launch_bounds__(384, 2) fused_kernel(
    const float* __restrict__ input,
    const float* __restrict__ w_om,
    const float* __restrict__ b_om,
    const float* __restrict__ bias,
    float* __restrict__ out,
    float* __restrict__ idx_out,
    float* __restrict__ mask_out)
{
    extern __shared__ float sm[];
    float*  sw   = sm;                        // [594][28]
    float*  rows = sm + 16632;                // 6 * 2 * 396
    float*  part = sm;                        // [5][27][128] (reuses sw)
    float*  omb  = sm + 21384;                // [27][128]
    int4*   sIdx = (int4*)sm;                 // [1152]   (phase C/D)
    float4* sWt  = (float4*)(sm + 4608);      // [1152]
    float*  cols = sm + 9216;                 // [2][36*128]

    const int tid = threadIdx.x;
    const int y   = blockIdx.x;
    const int b   = blockIdx.y;
    const float inv = 1.0f / 128.0f;

    // ---- phase A: stage om weights, transposed [(c*9+t)][oc] ----
    for (int i = tid; i < CHOM * KDIM; i += 384) {
        int oc  = i / KDIM;
        int rem = i - oc * KDIM;
        sw[rem * 28 + oc] = w_om[i];
    }

    // ---- phase B: om conv, 6 groups of 11 channels, thread = 2px x 28oc ----
    const int g   = tid >> 6;      // 0..5
    const int px  = tid & 63;      // pixels px and px+64
    const int cb0 = g * 11;

    float acc[56];
#pragma unroll
    for (int j = 0; j < 27; j++) {
        float bv = (g == 0) ? b_om[j] : 0.0f;
        acc[j] = bv; acc[28 + j] = bv;
    }
    acc[27] = 0.0f; acc[55] = 0.0f;

    auto stage = [&](int c, int buf) {
        float* dst = rows + (g * 2 + buf) * 396;
        for (int s = px; s < 390; s += 64) {
            int r  = s / 130;
            int i  = s - r * 130;
            int yy = y + r - 1;
            int xx = i - 1;
            float val = 0.0f;
            if (yy >= 0 && yy < Hh && xx >= 0 && xx < Ww) {
                if (c < Cin)       val = input[(((b * Cin) + c) * Hh + yy) * Ww + xx];
                else if (c == Cin) val = yy * inv;
                else               val = xx * inv - 0.5f;
            }
            dst[r * 132 + i] = val;
        }
    };

    stage(cb0, 0);
    __syncthreads();   // sw + first rows ready

    for (int ci = 0; ci < 11; ci++) {
        asm volatile("bar.sync %0, %1;" :: "r"(g + 1), "r"(64) : "memory");
        if (ci + 1 < 11) stage(cb0 + ci + 1, (ci + 1) & 1);
        const float* rb = rows + (g * 2 + (ci & 1)) * 396;
        const float* wc = sw + (cb0 + ci) * 252;
#pragma unroll
        for (int t = 0; t < 9; t++) {
            float v0 = rb[(t / 3) * 132 + px + (t % 3)];
            float v1 = rb[(t / 3) * 132 + px + 64 + (t % 3)];
            const float4* w4 = reinterpret_cast<const float4*>(wc + t * 28);
#pragma unroll
            for (int q = 0; q < 7; q++) {
                float4 wv = w4[q];
                acc[q * 4 + 0] += v0 * wv.x; acc[28 + q * 4 + 0] += v1 * wv.x;
                acc[q * 4 + 1] += v0 * wv.y; acc[28 + q * 4 + 1] += v1 * wv.y;
                acc[q * 4 + 2] += v0 * wv.z; acc[28 + q * 4 + 2] += v1 * wv.z;
                acc[q * 4 + 3] += v0 * wv.w; acc[28 + q * 4 + 3] += v1 * wv.w;
            }
        }
    }

    __syncthreads();   // all groups done reading sw
    if (g > 0) {
        float* pb = part + (g - 1) * 3456;
#pragma unroll
        for (int j = 0; j < 27; j++) {
            pb[j * 128 + px]      = acc[j];
            pb[j * 128 + px + 64] = acc[28 + j];
        }
    }
    __syncthreads();
    if (g == 0) {
#pragma unroll
        for (int j = 0; j < 27; j++) {
            float a0 = acc[j], a1 = acc[28 + j];
#pragma unroll
            for (int i = 0; i < 5; i++) {
                a0 += part[i * 3456 + j * 128 + px];
                a1 += part[i * 3456 + j * 128 + px + 64];
            }
            if (j < 9) {
                float bse = y * inv + (float)(j / 3 - 1);
                idx_out[((b * 18 + j) * Hh + y) * Ww + px]      = bse + a0;
                idx_out[((b * 18 + j) * Hh + y) * Ww + px + 64] = bse + a1;
                omb[j * 128 + px] = a0; omb[j * 128 + px + 64] = a1;
            } else if (j < 18) {
                int j2 = j - 9;
                float c0 = (float)px * inv - 0.5f + (float)(j2 % 3 - 1);
                float c1 = (float)(px + 64) * inv - 0.5f + (float)(j2 % 3 - 1);
                idx_out[((b * 18 + j) * Hh + y) * Ww + px]      = c0 + a0;
                idx_out[((b * 18 + j) * Hh + y) * Ww + px + 64] = c1 + a1;
                omb[j * 128 + px] = a0; omb[j * 128 + px + 64] = a1;
            } else {
                float s0 = 1.0f / (1.0f + __expf(-a0));
                float s1 = 1.0f / (1.0f + __expf(-a1));
                mask_out[((b * 9 + (j - 18)) * Hh + y) * Ww + px]      = s0;
                mask_out[((b * 9 + (j - 18)) * Hh + y) * Ww + px + 64] = s1;
                omb[j * 128 + px] = s0; omb[j * 128 + px + 64] = s1;
            }
        }
    }
    __syncthreads();

    // ---- phase C: bilinear corner tables (overwrites sw region) ----
    for (int q = tid; q < 9 * 128; q += 384) {
        int t = q >> 7;
        int p = q & 127;
        float oh = omb[(2 * t) * 128 + p];
        float ow = omb[(2 * t + 1) * 128 + p];
        float mk = omb[(18 + t) * 128 + p];

        float ph = oh + (float)(t / 3) + (float)(y - 1);
        float pw = ow + (float)(t % 3) + (float)(p - 1);
        float h0f = floorf(ph), w0f = floorf(pw);
        float lh = ph - h0f, lw = pw - w0f;
        float hh = 1.0f - lh, hw = 1.0f - lw;
        int h0 = (int)h0f, w0 = (int)w0f;
        int h1 = h0 + 1,   w1 = w0 + 1;
        float okh0 = (h0 >= 0 && h0 < Hh) ? 1.0f : 0.0f;
        float okh1 = (h1 >= 0 && h1 < Hh) ? 1.0f : 0.0f;
        float okw0 = (w0 >= 0 && w0 < Ww) ? 1.0f : 0.0f;
        float okw1 = (w1 >= 0 && w1 < Ww) ? 1.0f : 0.0f;
        float w00 = hh * hw * okh0 * okw0 * mk;
        float w01 = hh * lw * okh0 * okw1 * mk;
        float w10 = lh * hw * okh1 * okw0 * mk;
        float w11 = lh * lw * okh1 * okw1 * mk;
        int h0c = min(max(h0, 0), Hh - 1), h1c = min(max(h1, 0), Hh - 1);
        int w0c = min(max(w0, 0), Ww - 1), w1c = min(max(w1, 0), Ww - 1);

        sIdx[q] = make_int4(h0c * Ww, h1c * Ww, w0c, w1c);
        sWt[q]  = make_float4(w00, w01, w10, w11);
    }
    __syncthreads();

    // ---- phase D: warp-specialized gather + GEMM (4-channel chunks) ----
    const float* binp = input + b * Cin * HW;

    if (tid >= 256) {
        // producers (warps 8-11): one pixel per thread, 4 channels per chunk
        const int ptid = tid - 256;

        auto produce = [&](int cn, int buf) {
            float* dst = cols + buf * 4608 + ptid;
            if (cn < 16) {
                const float* pl0 = binp + (4 * cn) * HW;
#pragma unroll
                for (int t = 0; t < 9; t++) {
                    int q = t * 128 + ptid;
                    int4   id = sIdx[q];
                    float4 wt = sWt[q];
                    int a00 = id.x + id.z, a01 = id.x + id.w;
                    int a10 = id.y + id.z, a11 = id.y + id.w;
                    const float* pl = pl0;
#pragma unroll
                    for (int cc = 0; cc < 4; cc++, pl += HW) {
                        float v = wt.x * pl[a00] + wt.y * pl[a01]
                                + wt.z * pl[a10] + wt.w * pl[a11];
                        dst[(cc * 9 + t) * 128] = v;
                    }
                }
            } else {
#pragma unroll
                for (int t = 0; t < 9; t++) {
                    int q = t * 128 + ptid;
                    int4   id = sIdx[q];
                    float4 wt = sWt[q];
                    dst[t * 128] = ((wt.x + wt.y) * (float)(id.x >> 7)
                                  + (wt.z + wt.w) * (float)(id.y >> 7)) * inv;
                    dst[(9 + t) * 128] =
                          (wt.x + wt.z) * ((float)id.z * inv - 0.5f)
                        + (wt.y + wt.w) * ((float)id.w * inv - 0.5f);
                }
#pragma unroll
                for (int s = 18; s < 36; s++) dst[s * 128] = 0.0f;
            }
        };

        produce(0, 0);
        __syncthreads();
        for (int c = 0; c < NCHUNK; c++) {
            if (c + 1 < NCHUNK) produce(c + 1, (c + 1) & 1);
            __syncthreads();
        }
    } else {
        // consumers (warps 0-7): 8 oc x 4 px; og = warp id (uniform weight LDG)
        const int og = tid >> 5;
        const int pg = tid & 31;
        float dacc[8][4];
#pragma unroll
        for (int i = 0; i < 8; i++)
#pragma unroll
            for (int j = 0; j < 4; j++) dacc[i][j] = 0.0f;

        __syncthreads();   // matches producer's post-produce(0) barrier
        for (int c = 0; c < NCHUNK; c++) {
            const float* cbp = cols + (c & 1) * 4608 + pg * 4;
            const float* wb  = g_wt + (c * 36) * Cout + og * 8;
#pragma unroll 6
            for (int kk = 0; kk < 36; kk++) {
                float4 w0 = __ldg(reinterpret_cast<const float4*>(wb + kk * Cout));
                float4 w1 = __ldg(reinterpret_cast<const float4*>(wb + kk * Cout + 4));
                float4 cv = *reinterpret_cast<const float4*>(cbp + kk * 128);
                dacc[0][0] += w0.x * cv.x; dacc[0][1] += w0.x * cv.y;
                dacc[0][2] += w0.x * cv.z; dacc[0][3] += w0.x * cv.w;
                dacc[1][0] += w0.y * cv.x; dacc[1][1] += w0.y * cv.y;
                dacc[1][2] += w0.y * cv.z; dacc[1][3] += w0.y * cv.w;
                dacc[2][0] += w0.z * cv.x; dacc[2][1] += w0.z * cv.y;
                dacc[2][2] += w0.z * cv.z; dacc[2][3] += w0.z * cv.w;
                dacc[3][0] += w0.w * cv.x; dacc[3][1] += w0.w * cv.y;
                dacc[3][2] += w0.w * cv.z; dacc[3][3] += w0.w * cv.w;
                dacc[4][0] += w1.x * cv.x; dacc[4][1] += w1.x * cv.y;
                dacc[4][2] += w1.x * cv.z; dacc[4][3] += w1.x * cv.w;
                dacc[5][0] += w1.y * cv.x; dacc[5][1] += w1.y * cv.y;
                dacc[5][2] += w1.y * cv.z; dacc[5][3] += w1.y * cv.w;
                dacc[6][0] += w1.z * cv.x; dacc[6][1] += w1.z * cv.y;
                dacc[6][2] += w1.z * cv.z; dacc[6][3] += w1.z * cv.w;
                dacc[7][0] += w1.w * cv.x; dacc[7][1] += w1.w * cv.y;
                dacc[7][2] += w1.w * cv.z; dacc[7][3] += w1.w * cv.w;
            }
            __syncthreads();
        }

#pragma unroll
        for (int i = 0; i < 8; i++) {
            int oc = og * 8 + i;
            float bv = bias[oc];
            float4 o = make_float4(dacc[i][0] + bv, dacc[i][1] + bv,
                                   dacc[i][2] + bv, dacc[i][3] + bv);
            *reinterpret_cast<float4*>(
                out + ((b * Cout + oc) * Hh + y) * Ww + pg * 4) = o;
        }
    }
}

// ---------------- launcher ----------------
extern "C" void kernel_launch(void* const* d_in, const int* in_sizes, int n_in,
                              void* d_out, int out_size)
{
    const float* input  = (const float*)d_in[0];
    const float* weight = (const float*)d_in[1];
    const float* bias   = (const float*)d_in[2];
    const float* w_om   = (const float*)d_in[3];
    const float* b_om   = (const float*)d_in[4];

    float* out      = (float*)d_out;
    float* idx_out  = out + (size_t)Bn * Cout * Hh * Ww;
    float* mask_out = idx_out + (size_t)Bn * 18 * Hh * Ww;

    const int smF = 24840 * 4;   // 99,360 B
    cudaFuncSetAttribute(fused_kernel, cudaFuncAttributeMaxDynamicSharedMemorySize, smF);

    prep_wt_kernel<<<(KPAD * Cout + 255) / 256, 256>>>(weight);
    fused_kernel<<<dim3(Hh, Bn), 384, smF>>>(input, w_om, b_om, bias,
                                             out, idx_out, mask_out);
}